// round 4
// baseline (speedup 1.0000x reference)
#include <cuda_runtime.h>
#include <cuda_bf16.h>
#include <stdint.h>

#define B_    64
#define H_    6
#define N_    512
#define D_    32
#define NIDX  43           // used bias-table rows
#define BH_   (B_*H_)      // 384
#define CH_   128          // KV rows per chunk
#define NCH   4            // chunks
#define LOG2E 1.4426950408889634f

// smem layout (16B units):
//   Kbuf: 2 bufs x 128 rows x 12 units (8 used + 4 pad -> 192B row stride)
//   Vbuf: 2 bufs x 32 rows x 36 units (32 used + 4 pad -> 576B row stride)
#define KROW_U   12
#define KBUF_U   (CH_*KROW_U)          // 1536
#define VROW_U   36
#define VBUF_U   (D_*VROW_U)           // 1152
#define SMEM_U   (2*KBUF_U + 2*VBUF_U) // 5376 units
#define SMEM_BYTES (SMEM_U*16 + 192)   // ~86.2 KB -> 2 CTAs/SM

// pre-split K/V in gmem, layout mirrors smem (dense, 8 / 32 units per row)
__device__ uint4 g_Ksplit[BH_ * NCH * CH_ * 8];   // 25.2 MB
__device__ uint4 g_Vsplit[BH_ * NCH * D_ * 32];   // 25.2 MB
__device__ float g_pos[H_ * NIDX];

// ---------------------------------------------------------------------------
// helpers
// ---------------------------------------------------------------------------
__device__ __forceinline__ void split2(float x0, float x1, uint32_t& hi, uint32_t& lo) {
    uint32_t h;
    asm("cvt.rn.bf16x2.f32 %0, %1, %2;" : "=r"(h) : "f"(x1), "f"(x0));
    float h0 = __uint_as_float(h << 16);
    float h1 = __uint_as_float(h & 0xffff0000u);
    asm("cvt.rn.bf16x2.f32 %0, %1, %2;" : "=r"(lo) : "f"(x1 - h1), "f"(x0 - h0));
    hi = h;
}

__device__ __forceinline__ float ex2(float x) {
    float y; asm("ex2.approx.f32 %0, %1;" : "=f"(y) : "f"(x)); return y;
}

__device__ __forceinline__ void mma_bf16(float c[4], const uint32_t a[4], const uint32_t b[2]) {
    asm volatile(
        "mma.sync.aligned.m16n8k16.row.col.f32.bf16.bf16.f32 "
        "{%0,%1,%2,%3}, {%4,%5,%6,%7}, {%8,%9}, {%0,%1,%2,%3};\n"
        : "+f"(c[0]), "+f"(c[1]), "+f"(c[2]), "+f"(c[3])
        : "r"(a[0]), "r"(a[1]), "r"(a[2]), "r"(a[3]), "r"(b[0]), "r"(b[1]));
}

__device__ __forceinline__ void cp16(uint32_t dst, const void* src) {
    asm volatile("cp.async.cg.shared.global [%0], [%1], 16;" :: "r"(dst), "l"(src));
}

// ---------------------------------------------------------------------------
// Kernel 0: 43-row dynamic position-bias MLP
// ---------------------------------------------------------------------------
__device__ __forceinline__ void ln_relu12(const float* x, const float* g, const float* b, float* y) {
    float mu = 0.f;
    #pragma unroll
    for (int j = 0; j < 12; j++) mu += x[j];
    mu *= (1.f / 12.f);
    float var = 0.f;
    #pragma unroll
    for (int j = 0; j < 12; j++) { float d = x[j] - mu; var += d * d; }
    var *= (1.f / 12.f);
    float inv = rsqrtf(var + 1e-5f);
    #pragma unroll
    for (int j = 0; j < 12; j++) {
        float t = (x[j] - mu) * inv * g[j] + b[j];
        y[j] = t > 0.f ? t : 0.f;
    }
}

__global__ void pos_mlp_kernel(
    const float* __restrict__ pw,  const float* __restrict__ pb,
    const float* __restrict__ g1,  const float* __restrict__ b1,
    const float* __restrict__ w1,  const float* __restrict__ bb1,
    const float* __restrict__ g2,  const float* __restrict__ b2,
    const float* __restrict__ w2,  const float* __restrict__ bb2,
    const float* __restrict__ g3,  const float* __restrict__ b3,
    const float* __restrict__ w3,  const float* __restrict__ bb3)
{
    int r = threadIdx.x;
    if (r >= NIDX) return;
    float c0 = -7.0f;
    float c1 = (float)(r / 15) - 7.0f;
    float c2 = (float)(r % 15) - 7.0f;

    float x[12], y[12];
    #pragma unroll
    for (int j = 0; j < 12; j++)
        x[j] = c0 * pw[j] + c1 * pw[12 + j] + c2 * pw[24 + j] + pb[j];

    ln_relu12(x, g1, b1, y);
    #pragma unroll
    for (int j = 0; j < 12; j++) {
        float s = bb1[j];
        #pragma unroll
        for (int i = 0; i < 12; i++) s += y[i] * w1[i * 12 + j];
        x[j] = s;
    }
    ln_relu12(x, g2, b2, y);
    #pragma unroll
    for (int j = 0; j < 12; j++) {
        float s = bb2[j];
        #pragma unroll
        for (int i = 0; i < 12; i++) s += y[i] * w2[i * 12 + j];
        x[j] = s;
    }
    ln_relu12(x, g3, b3, y);
    #pragma unroll
    for (int h = 0; h < H_; h++) {
        float s = bb3[h];
        #pragma unroll
        for (int i = 0; i < 12; i++) s += y[i] * w3[i * H_ + h];
        g_pos[h * NIDX + r] = s;
    }
}

// ---------------------------------------------------------------------------
// Kernel 1: pre-split K/V into interleaved (hi0,hi1,lo0,lo1) 16B words
// ---------------------------------------------------------------------------
__global__ __launch_bounds__(256) void split_kv_kernel(
    const float* __restrict__ k, const float* __restrict__ v)
{
    __shared__ float vs[CH_ * 33];
    const int bh = blockIdx.x;
    const int tid = threadIdx.x;
    const float* kb = k + (size_t)bh * N_ * D_;
    const float* vb = v + (size_t)bh * N_ * D_;

    for (int ch = 0; ch < NCH; ch++) {
        // K: direct from gmem rows (row-major, contiguous)
        for (int i = tid; i < CH_ * 8; i += 256) {
            int n2 = i >> 3, u = i & 7;
            int ks = u >> 2, le = u & 3;
            const float* row = kb + (size_t)(ch * CH_ + n2) * D_;
            int c0 = ks * 16 + le * 2;
            float a0 = row[c0], a1 = row[c0 + 1], a2 = row[c0 + 8], a3 = row[c0 + 9];
            uint4 w;
            split2(a0, a1, w.x, w.z);
            split2(a2, a3, w.y, w.w);
            g_Ksplit[(size_t)(bh * NCH + ch) * (CH_ * 8) + i] = w;
        }
        // V: stage chunk in smem (coalesced), then transpose-gather
        __syncthreads();
        for (int i = tid; i < CH_ * D_; i += 256) {
            int kv = i >> 5, d = i & 31;
            vs[kv * 33 + d] = vb[(size_t)(ch * CH_) * D_ + i];
        }
        __syncthreads();
        for (int i = tid; i < D_ * 32; i += 256) {
            int d = i >> 5, w_ = i & 31;
            int kkloc = w_ >> 2, le = w_ & 3;
            int kv0 = kkloc * 16 + le * 2;
            float a0 = vs[kv0 * 33 + d];
            float a1 = vs[(kv0 + 1) * 33 + d];
            float a2 = vs[(kv0 + 8) * 33 + d];
            float a3 = vs[(kv0 + 9) * 33 + d];
            uint4 w;
            split2(a0, a1, w.x, w.z);
            split2(a2, a3, w.y, w.w);
            g_Vsplit[(size_t)(bh * NCH + ch) * (D_ * 32) + i] = w;
        }
        __syncthreads();
    }
}

// ---------------------------------------------------------------------------
// Kernel 2: flash attention, split-bf16 3-pass MMA, cp.async pipelined chunks
// ---------------------------------------------------------------------------
__global__ __launch_bounds__(256, 2) void attn_kernel(
    const float* __restrict__ q, float* __restrict__ out)
{
    extern __shared__ uint4 smem4[];
    float* biasSm = (float*)(smem4 + SMEM_U);

    const int qt = blockIdx.x, head = blockIdx.y, batch = blockIdx.z;
    const int bh = batch * H_ + head;
    const size_t bhOff = (size_t)bh * N_ * D_;
    const float* qb = q + bhOff;
    const int tid = threadIdx.x;

    uint32_t smem_u32;
    asm("{ .reg .u64 t; cvta.to.shared.u64 t, %1; cvt.u32.u64 %0, t; }"
        : "=r"(smem_u32) : "l"(smem4));

    if (tid < NIDX) biasSm[tid] = g_pos[head * NIDX + tid] * LOG2E;

    const int warp = tid >> 5, lane = tid & 31;
    const int lq = lane >> 2;
    const int le = lane & 3;
    const int e0 = le * 2;
    const int r0 = qt * 128 + warp * 16 + lq;
    const int r1 = r0 + 8;
    const int sq0 = (r0 >> 6) + ((r0 >> 3) & 7) + (r0 & 7);
    const int sq1 = (r1 >> 6) + ((r1 >> 3) & 7) + (r1 & 7);

    // --- fill chunk 0 (cp.async) ---
    const int bh4 = bh * NCH;
    {
        const uint4* gk = g_Ksplit + (size_t)bh4 * (CH_ * 8);
        uint32_t kd = smem_u32;
        for (int i = tid; i < CH_ * 8; i += 256) {
            int n2 = i >> 3, u = i & 7;
            cp16(kd + (n2 * KROW_U + u) * 16, gk + i);
        }
        const uint4* gv = g_Vsplit + (size_t)bh4 * (D_ * 32);
        uint32_t vd = smem_u32 + 2 * KBUF_U * 16;
        for (int i = tid; i < D_ * 32; i += 256) {
            int d = i >> 5, w_ = i & 31;
            cp16(vd + (d * VROW_U + w_) * 16, gv + i);
        }
        asm volatile("cp.async.commit_group;" ::: "memory");
    }

    // --- Q A-fragments (scaled into log2 domain, split) ---
    const float scale = 0.17677669529663687f * LOG2E;
    uint32_t aqh[2][4], aql[2][4];
    #pragma unroll
    for (int ks = 0; ks < 2; ks++) {
        int cb = ks * 16 + e0;
        split2(qb[(size_t)r0 * D_ + cb] * scale,     qb[(size_t)r0 * D_ + cb + 1] * scale, aqh[ks][0], aql[ks][0]);
        split2(qb[(size_t)r1 * D_ + cb] * scale,     qb[(size_t)r1 * D_ + cb + 1] * scale, aqh[ks][1], aql[ks][1]);
        split2(qb[(size_t)r0 * D_ + cb + 8] * scale, qb[(size_t)r0 * D_ + cb + 9] * scale, aqh[ks][2], aql[ks][2]);
        split2(qb[(size_t)r1 * D_ + cb + 8] * scale, qb[(size_t)r1 * D_ + cb + 9] * scale, aqh[ks][3], aql[ks][3]);
    }

    float O[4][4];
    #pragma unroll
    for (int d = 0; d < 4; d++)
        #pragma unroll
        for (int j = 0; j < 4; j++) O[d][j] = 0.f;
    float m0 = -1e30f, m1 = -1e30f, l0 = 0.f, l1 = 0.f;

    for (int ch = 0; ch < NCH; ch++) {
        // prefetch next chunk into the other buffer
        if (ch + 1 < NCH) {
            int b = (ch + 1) & 1;
            const uint4* gk = g_Ksplit + (size_t)(bh4 + ch + 1) * (CH_ * 8);
            uint32_t kd = smem_u32 + b * KBUF_U * 16;
            for (int i = tid; i < CH_ * 8; i += 256) {
                int n2 = i >> 3, u = i & 7;
                cp16(kd + (n2 * KROW_U + u) * 16, gk + i);
            }
            const uint4* gv = g_Vsplit + (size_t)(bh4 + ch + 1) * (D_ * 32);
            uint32_t vd = smem_u32 + (2 * KBUF_U + b * VBUF_U) * 16;
            for (int i = tid; i < D_ * 32; i += 256) {
                int d = i >> 5, w_ = i & 31;
                cp16(vd + (d * VROW_U + w_) * 16, gv + i);
            }
            asm volatile("cp.async.commit_group;" ::: "memory");
            asm volatile("cp.async.wait_group 1;" ::: "memory");
        } else {
            asm volatile("cp.async.wait_group 0;" ::: "memory");
        }
        __syncthreads();

        const uint4* Kb = smem4 + (ch & 1) * KBUF_U;
        const uint4* Vb = smem4 + 2 * KBUF_U + (ch & 1) * VBUF_U;

        #pragma unroll
        for (int c4 = 0; c4 < 2; c4++) {
            const int ch64 = ch * 2 + c4;
            float S[8][4];
            #pragma unroll
            for (int nt = 0; nt < 8; nt++) {
                int sk = ch64 + nt + e0;
                S[nt][0] = biasSm[sq0 - sk + 21];
                S[nt][1] = biasSm[sq0 - sk + 20];
                S[nt][2] = biasSm[sq1 - sk + 21];
                S[nt][3] = biasSm[sq1 - sk + 20];
            }
            // --- S += (Q K^T) * scale' (3-pass split bf16), one LDS.128 per frag ---
            #pragma unroll
            for (int nt = 0; nt < 8; nt++) {
                int n = c4 * 64 + nt * 8 + lq;
                #pragma unroll
                for (int ks = 0; ks < 2; ks++) {
                    uint4 w = Kb[n * KROW_U + ks * 4 + le];
                    uint32_t bhh[2] = {w.x, w.y};
                    uint32_t bll[2] = {w.z, w.w};
                    mma_bf16(S[nt], aqh[ks], bhh);
                    mma_bf16(S[nt], aqh[ks], bll);
                    mma_bf16(S[nt], aql[ks], bhh);
                }
            }
            // --- online softmax (log2 domain) ---
            float mx0 = -1e30f, mx1 = -1e30f;
            #pragma unroll
            for (int nt = 0; nt < 8; nt++) {
                mx0 = fmaxf(mx0, fmaxf(S[nt][0], S[nt][1]));
                mx1 = fmaxf(mx1, fmaxf(S[nt][2], S[nt][3]));
            }
            mx0 = fmaxf(mx0, __shfl_xor_sync(0xffffffffu, mx0, 1));
            mx0 = fmaxf(mx0, __shfl_xor_sync(0xffffffffu, mx0, 2));
            mx1 = fmaxf(mx1, __shfl_xor_sync(0xffffffffu, mx1, 1));
            mx1 = fmaxf(mx1, __shfl_xor_sync(0xffffffffu, mx1, 2));
            float mn0 = fmaxf(m0, mx0), mn1 = fmaxf(m1, mx1);
            float al0 = ex2(m0 - mn0), al1 = ex2(m1 - mn1);
            m0 = mn0; m1 = mn1;
            l0 *= al0; l1 *= al1;
            #pragma unroll
            for (int d = 0; d < 4; d++) {
                O[d][0] *= al0; O[d][1] *= al0;
                O[d][2] *= al1; O[d][3] *= al1;
            }
            float ps0 = 0.f, ps1 = 0.f;
            #pragma unroll
            for (int nt = 0; nt < 8; nt++) {
                S[nt][0] = ex2(S[nt][0] - mn0); S[nt][1] = ex2(S[nt][1] - mn0);
                S[nt][2] = ex2(S[nt][2] - mn1); S[nt][3] = ex2(S[nt][3] - mn1);
                ps0 += S[nt][0] + S[nt][1];
                ps1 += S[nt][2] + S[nt][3];
            }
            l0 += ps0; l1 += ps1;
            // --- O += P V (3-pass split bf16) ---
            #pragma unroll
            for (int kk = 0; kk < 4; kk++) {
                uint32_t ah[4], al_[4];
                split2(S[2 * kk][0],     S[2 * kk][1],     ah[0], al_[0]);
                split2(S[2 * kk][2],     S[2 * kk][3],     ah[1], al_[1]);
                split2(S[2 * kk + 1][0], S[2 * kk + 1][1], ah[2], al_[2]);
                split2(S[2 * kk + 1][2], S[2 * kk + 1][3], ah[3], al_[3]);
                int kkloc = c4 * 4 + kk;
                #pragma unroll
                for (int dt = 0; dt < 4; dt++) {
                    uint4 w = Vb[(dt * 8 + lq) * VROW_U + kkloc * 4 + le];
                    uint32_t bhh[2] = {w.x, w.y};
                    uint32_t bll[2] = {w.z, w.w};
                    mma_bf16(O[dt], ah,  bhh);
                    mma_bf16(O[dt], ah,  bll);
                    mma_bf16(O[dt], al_, bhh);
                }
            }
        }
        __syncthreads();
    }

    // --- finalize ---
    l0 += __shfl_xor_sync(0xffffffffu, l0, 1);
    l0 += __shfl_xor_sync(0xffffffffu, l0, 2);
    l1 += __shfl_xor_sync(0xffffffffu, l1, 1);
    l1 += __shfl_xor_sync(0xffffffffu, l1, 2);
    float i0 = 1.f / l0, i1 = 1.f / l1;
    float* ob = out + bhOff;
    #pragma unroll
    for (int dt = 0; dt < 4; dt++) {
        int c = dt * 8 + e0;
        float2 o01; o01.x = O[dt][0] * i0; o01.y = O[dt][1] * i0;
        float2 o23; o23.x = O[dt][2] * i1; o23.y = O[dt][3] * i1;
        *(float2*)(ob + (size_t)r0 * D_ + c) = o01;
        *(float2*)(ob + (size_t)r1 * D_ + c) = o23;
    }
}

// ---------------------------------------------------------------------------
extern "C" void kernel_launch(void* const* d_in, const int* in_sizes, int n_in,
                              void* d_out, int out_size)
{
    const float* q = (const float*)d_in[0];
    const float* k = (const float*)d_in[1];
    const float* v = (const float*)d_in[2];
    int base = (in_sizes[3] == 36) ? 3 : 6;
    const float* pw  = (const float*)d_in[base + 0];
    const float* pb  = (const float*)d_in[base + 1];
    const float* g1  = (const float*)d_in[base + 2];
    const float* b1  = (const float*)d_in[base + 3];
    const float* w1  = (const float*)d_in[base + 4];
    const float* bb1 = (const float*)d_in[base + 5];
    const float* g2  = (const float*)d_in[base + 6];
    const float* b2  = (const float*)d_in[base + 7];
    const float* w2  = (const float*)d_in[base + 8];
    const float* bb2 = (const float*)d_in[base + 9];
    const float* g3  = (const float*)d_in[base + 10];
    const float* b3  = (const float*)d_in[base + 11];
    const float* w3  = (const float*)d_in[base + 12];
    const float* bb3 = (const float*)d_in[base + 13];
    float* out = (float*)d_out;

    cudaFuncSetAttribute(attn_kernel, cudaFuncAttributeMaxDynamicSharedMemorySize, SMEM_BYTES);

    pos_mlp_kernel<<<1, 64>>>(pw, pb, g1, b1, w1, bb1, g2, b2, w2, bb2, g3, b3, w3, bb3);
    split_kv_kernel<<<BH_, 256>>>(k, v);

    dim3 grid(N_ / 128, H_, B_);
    attn_kernel<<<grid, 256, SMEM_BYTES>>>(q, out);
}

// round 6
// speedup vs baseline: 1.5330x; 1.5330x over previous
#include <cuda_runtime.h>
#include <cuda_fp16.h>
#include <stdint.h>

#define B_    64
#define H_    6
#define N_    512
#define D_    32
#define NIDX  43
#define BH_   384
#define CH_   128          // kv rows per chunk
#define NCH   4
#define LOG2E 1.4426950408889634f

// smem (bytes): K bufs 2x8KB | V bufs 2x18KB (576B rows) | bias
#define SK_OFF   0
#define SV_OFF   16384
#define SB_OFF   53248
#define SMEM_SZ  53440
#define VROW_U   36        // uint4 per V^T d-row (32 used + 4 pad)

// gmem images: K fp16 single [bh][ch][n(128)][le(4)]u4 ; V fp16 split [bh][ch][d(32)][kk(8)][le(4)]u4
__device__ uint4 g_K[BH_ * NCH * CH_ * 4];
__device__ uint4 g_V[BH_ * NCH * D_ * 32];
__device__ float g_pos[H_ * NIDX];

// ---------------- helpers ----------------
__device__ __forceinline__ uint32_t pkf16(float x0, float x1) {
    uint32_t r; asm("cvt.rn.f16x2.f32 %0, %1, %2;" : "=r"(r) : "f"(x1), "f"(x0)); return r;
}
__device__ __forceinline__ void splitf16(float x0, float x1, uint32_t& hi, uint32_t& lo) {
    hi = pkf16(x0, x1);
    __half2 h = *reinterpret_cast<__half2*>(&hi);
    lo = pkf16(x0 - __half2float(h.x), x1 - __half2float(h.y));
}
__device__ __forceinline__ float ex2f(float x) {
    float y; asm("ex2.approx.f32 %0, %1;" : "=f"(y) : "f"(x)); return y;
}
__device__ __forceinline__ void mma_f16(float c[4], const uint32_t a[4], const uint32_t b[2]) {
    asm volatile(
        "mma.sync.aligned.m16n8k16.row.col.f32.f16.f16.f32 "
        "{%0,%1,%2,%3}, {%4,%5,%6,%7}, {%8,%9}, {%0,%1,%2,%3};\n"
        : "+f"(c[0]), "+f"(c[1]), "+f"(c[2]), "+f"(c[3])
        : "r"(a[0]), "r"(a[1]), "r"(a[2]), "r"(a[3]), "r"(b[0]), "r"(b[1]));
}
__device__ __forceinline__ void cp16(uint32_t dst, const void* src) {
    asm volatile("cp.async.cg.shared.global [%0], [%1], 16;" :: "r"(dst), "l"(src));
}
#define CP_COMMIT() asm volatile("cp.async.commit_group;" ::: "memory")
#define CP_WAIT(n)  asm volatile("cp.async.wait_group %0;" :: "n"(n) : "memory")

// ---------------------------------------------------------------------------
// Kernel 0: prep — block 0 runs bias MLP; blocks 1..384 build K/V fp16 images
// ---------------------------------------------------------------------------
__device__ __forceinline__ void ln_relu12(const float* x, const float* g, const float* b, float* y) {
    float mu = 0.f;
    #pragma unroll
    for (int j = 0; j < 12; j++) mu += x[j];
    mu *= (1.f / 12.f);
    float var = 0.f;
    #pragma unroll
    for (int j = 0; j < 12; j++) { float d = x[j] - mu; var += d * d; }
    var *= (1.f / 12.f);
    float inv = rsqrtf(var + 1e-5f);
    #pragma unroll
    for (int j = 0; j < 12; j++) {
        float t = (x[j] - mu) * inv * g[j] + b[j];
        y[j] = t > 0.f ? t : 0.f;
    }
}

__global__ __launch_bounds__(256) void prep_kernel(
    const float* __restrict__ k, const float* __restrict__ v,
    const float* __restrict__ pw,  const float* __restrict__ pb,
    const float* __restrict__ g1,  const float* __restrict__ b1,
    const float* __restrict__ w1,  const float* __restrict__ bb1,
    const float* __restrict__ g2,  const float* __restrict__ b2,
    const float* __restrict__ w2,  const float* __restrict__ bb2,
    const float* __restrict__ g3,  const float* __restrict__ b3,
    const float* __restrict__ w3,  const float* __restrict__ bb3)
{
    __shared__ float sh[CH_ * 33];
    const int t = threadIdx.x;

    if (blockIdx.x == 0) {
        if (t < 36)  sh[t] = pw[t];
        if (t < 12) {
            sh[36+t]=pb[t];  sh[48+t]=g1[t]; sh[60+t]=b1[t]; sh[216+t]=bb1[t];
            sh[228+t]=g2[t]; sh[240+t]=b2[t]; sh[396+t]=bb2[t];
            sh[408+t]=g3[t]; sh[420+t]=b3[t];
        }
        if (t < 144) { sh[72+t]=w1[t]; sh[252+t]=w2[t]; }
        if (t < 72)  sh[432+t] = w3[t];
        if (t < 6)   sh[504+t] = bb3[t];
        __syncthreads();
        if (t < NIDX) {
            float c0 = -7.0f, c1 = (float)(t / 15) - 7.0f, c2 = (float)(t % 15) - 7.0f;
            float x[12], y[12];
            #pragma unroll
            for (int j = 0; j < 12; j++)
                x[j] = c0 * sh[j] + c1 * sh[12 + j] + c2 * sh[24 + j] + sh[36 + j];
            ln_relu12(x, sh+48, sh+60, y);
            #pragma unroll
            for (int j = 0; j < 12; j++) {
                float s = sh[216 + j];
                #pragma unroll
                for (int i = 0; i < 12; i++) s += y[i] * sh[72 + i * 12 + j];
                x[j] = s;
            }
            ln_relu12(x, sh+228, sh+240, y);
            #pragma unroll
            for (int j = 0; j < 12; j++) {
                float s = sh[396 + j];
                #pragma unroll
                for (int i = 0; i < 12; i++) s += y[i] * sh[252 + i * 12 + j];
                x[j] = s;
            }
            ln_relu12(x, sh+408, sh+420, y);
            #pragma unroll
            for (int h = 0; h < H_; h++) {
                float s = sh[504 + h];
                #pragma unroll
                for (int i = 0; i < 12; i++) s += y[i] * sh[432 + i * H_ + h];
                g_pos[h * NIDX + t] = s;
            }
        }
        return;
    }

    const int bh = blockIdx.x - 1;
    const float* kb = k + (size_t)bh * N_ * D_;
    const float* vb = v + (size_t)bh * N_ * D_;

    // K image: word [n][le] = f16{k[c0],k[c0+1]},{k[c0+8],k[c0+9]},{k[16+c0],k[16+c0+1]},{k[16+c0+8],k[16+c0+9]}
    for (int i = t; i < N_ * 4; i += 256) {
        int n = i >> 2, le = i & 3, c0 = le * 2;
        const float* row = kb + (size_t)n * D_;
        float2 f0 = *(const float2*)(row + c0);
        float2 f1 = *(const float2*)(row + c0 + 8);
        float2 f2 = *(const float2*)(row + c0 + 16);
        float2 f3 = *(const float2*)(row + c0 + 24);
        uint4 w;
        w.x = pkf16(f0.x, f0.y); w.y = pkf16(f1.x, f1.y);
        w.z = pkf16(f2.x, f2.y); w.w = pkf16(f3.x, f3.y);
        g_K[(size_t)bh * (N_ * 4) + i] = w;
    }

    // V image per chunk: word [d][kk][le] = {hi(v0,v1), hi(v8,v9), lo(v0,v1), lo(v8,v9)}
    for (int ch = 0; ch < NCH; ch++) {
        __syncthreads();
        for (int i = t; i < CH_ * D_; i += 256) {
            int kv = i >> 5, d = i & 31;
            sh[kv * 33 + d] = vb[(size_t)(ch * CH_) * D_ + i];
        }
        __syncthreads();
        for (int i = t; i < D_ * 32; i += 256) {
            int d = i >> 5, wi = i & 31, kk = wi >> 2, le = wi & 3;
            int k0 = kk * 16 + le * 2;
            float v0 = sh[k0 * 33 + d],       v1 = sh[(k0 + 1) * 33 + d];
            float v8 = sh[(k0 + 8) * 33 + d], v9 = sh[(k0 + 9) * 33 + d];
            uint4 w;
            splitf16(v0, v1, w.x, w.z);
            splitf16(v8, v9, w.y, w.w);
            g_V[(size_t)(bh * NCH + ch) * (D_ * 32) + i] = w;
        }
    }
}

// ---------------------------------------------------------------------------
// Kernel 1: flash attention — fp16 2+2 pass, no-max softmax, cp.async pipeline
// ---------------------------------------------------------------------------
__global__ __launch_bounds__(256, 2) void attn_kernel(
    const float* __restrict__ q, float* __restrict__ out)
{
    extern __shared__ unsigned char smem[];
    uint32_t sb;
    asm("{ .reg .u64 t; cvta.to.shared.u64 t, %1; cvt.u32.u64 %0, t; }" : "=r"(sb) : "l"(smem));
    float* biasSm = (float*)(smem + SB_OFF);

    const int qt = blockIdx.x, head = blockIdx.y, batch = blockIdx.z;
    const int bh = batch * H_ + head;
    const size_t bhOff = (size_t)bh * N_ * D_;
    const float* qb = q + bhOff;
    const int tid = threadIdx.x;

    if (tid < NIDX) biasSm[tid] = g_pos[head * NIDX + tid] * LOG2E;

    // chunk 0 fill
    {
        const uint4* gk = g_K + (size_t)bh * (N_ * 4);
        const uint4* gv = g_V + (size_t)(bh * NCH) * (D_ * 32);
        for (int i = tid; i < CH_ * 4; i += 256) cp16(sb + SK_OFF + i * 16, gk + i);
        for (int i = tid; i < D_ * 32; i += 256) {
            int d = i >> 5, wi = i & 31;
            cp16(sb + SV_OFF + (d * VROW_U + wi) * 16, gv + i);
        }
        CP_COMMIT();
    }

    const int warp = tid >> 5, lane = tid & 31;
    const int lq = lane >> 2, le = lane & 3, e0 = le * 2;
    const int r0 = qt * 128 + warp * 16 + lq;
    const int r1 = r0 + 8;
    const int sq0 = (r0 >> 6) + ((r0 >> 3) & 7) + (r0 & 7);
    const int sq1 = (r1 >> 6) + ((r1 >> 3) & 7) + (r1 & 7);

    // Q fragments: fp16 split, scale folded into log2 domain
    const float scale = 0.17677669529663687f * LOG2E;
    uint32_t aqh[2][4], aql[2][4];
    #pragma unroll
    for (int ks = 0; ks < 2; ks++) {
        int cb = ks * 16 + e0;
        splitf16(qb[(size_t)r0 * D_ + cb] * scale,     qb[(size_t)r0 * D_ + cb + 1] * scale, aqh[ks][0], aql[ks][0]);
        splitf16(qb[(size_t)r1 * D_ + cb] * scale,     qb[(size_t)r1 * D_ + cb + 1] * scale, aqh[ks][1], aql[ks][1]);
        splitf16(qb[(size_t)r0 * D_ + cb + 8] * scale, qb[(size_t)r0 * D_ + cb + 9] * scale, aqh[ks][2], aql[ks][2]);
        splitf16(qb[(size_t)r1 * D_ + cb + 8] * scale, qb[(size_t)r1 * D_ + cb + 9] * scale, aqh[ks][3], aql[ks][3]);
    }

    float O[4][4];
    #pragma unroll
    for (int d = 0; d < 4; d++)
        #pragma unroll
        for (int j = 0; j < 4; j++) O[d][j] = 0.f;
    float l0 = 0.f, l1 = 0.f;

    for (int ch = 0; ch < NCH; ch++) {
        if (ch + 1 < NCH) {
            int b = (ch + 1) & 1;
            const uint4* gk = g_K + (size_t)bh * (N_ * 4) + (ch + 1) * (CH_ * 4);
            const uint4* gv = g_V + (size_t)(bh * NCH + ch + 1) * (D_ * 32);
            uint32_t kd = sb + SK_OFF + b * 8192;
            uint32_t vd = sb + SV_OFF + b * 18432;
            for (int i = tid; i < CH_ * 4; i += 256) cp16(kd + i * 16, gk + i);
            for (int i = tid; i < D_ * 32; i += 256) {
                int d = i >> 5, wi = i & 31;
                cp16(vd + (d * VROW_U + wi) * 16, gv + i);
            }
            CP_COMMIT();
            CP_WAIT(1);
        } else {
            CP_WAIT(0);
        }
        __syncthreads();

        const uint4* Kb = (const uint4*)(smem + SK_OFF + (ch & 1) * 8192);
        const uint4* Vb = (const uint4*)(smem + SV_OFF + (ch & 1) * 18432);

        #pragma unroll
        for (int c4 = 0; c4 < 2; c4++) {
            const int ch64 = ch * 2 + c4;
            float S[8][4];
            #pragma unroll
            for (int nt = 0; nt < 8; nt++) {
                int sk = ch64 + nt + e0;
                S[nt][0] = biasSm[sq0 - sk + 21];
                S[nt][1] = biasSm[sq0 - sk + 20];
                S[nt][2] = biasSm[sq1 - sk + 21];
                S[nt][3] = biasSm[sq1 - sk + 20];
            }
            // S += Q K^T : 2-pass (Q hi/lo fp16, K single fp16)
            #pragma unroll
            for (int nt = 0; nt < 8; nt++) {
                int n = c4 * 64 + nt * 8 + lq;
                uint4 w = Kb[n * 4 + le];
                uint32_t b0[2] = {w.x, w.y};
                uint32_t b1[2] = {w.z, w.w};
                mma_f16(S[nt], aqh[0], b0);
                mma_f16(S[nt], aql[0], b0);
                mma_f16(S[nt], aqh[1], b1);
                mma_f16(S[nt], aql[1], b1);
            }
            // softmax (log2 domain, no max needed: logits bounded)
            float ps0 = 0.f, ps1 = 0.f;
            #pragma unroll
            for (int nt = 0; nt < 8; nt++) {
                S[nt][0] = ex2f(S[nt][0]); S[nt][1] = ex2f(S[nt][1]);
                S[nt][2] = ex2f(S[nt][2]); S[nt][3] = ex2f(S[nt][3]);
                ps0 += S[nt][0] + S[nt][1];
                ps1 += S[nt][2] + S[nt][3];
            }
            l0 += ps0; l1 += ps1;
            // O += P V : 2-pass (P single fp16, V hi/lo fp16)
            #pragma unroll
            for (int kk = 0; kk < 4; kk++) {
                uint32_t ap[4];
                ap[0] = pkf16(S[2 * kk][0],     S[2 * kk][1]);
                ap[1] = pkf16(S[2 * kk][2],     S[2 * kk][3]);
                ap[2] = pkf16(S[2 * kk + 1][0], S[2 * kk + 1][1]);
                ap[3] = pkf16(S[2 * kk + 1][2], S[2 * kk + 1][3]);
                int kkloc = c4 * 4 + kk;
                #pragma unroll
                for (int dt = 0; dt < 4; dt++) {
                    uint4 w = Vb[(dt * 8 + lq) * VROW_U + kkloc * 4 + le];
                    uint32_t bh_[2] = {w.x, w.y};
                    uint32_t bl_[2] = {w.z, w.w};
                    mma_f16(O[dt], ap, bh_);
                    mma_f16(O[dt], ap, bl_);
                }
            }
        }
        __syncthreads();
    }

    // finalize
    l0 += __shfl_xor_sync(0xffffffffu, l0, 1);
    l0 += __shfl_xor_sync(0xffffffffu, l0, 2);
    l1 += __shfl_xor_sync(0xffffffffu, l1, 1);
    l1 += __shfl_xor_sync(0xffffffffu, l1, 2);
    float i0 = 1.f / l0, i1 = 1.f / l1;
    float* ob = out + bhOff;
    #pragma unroll
    for (int dt = 0; dt < 4; dt++) {
        int c = dt * 8 + e0;
        float2 o01; o01.x = O[dt][0] * i0; o01.y = O[dt][1] * i0;
        float2 o23; o23.x = O[dt][2] * i1; o23.y = O[dt][3] * i1;
        *(float2*)(ob + (size_t)r0 * D_ + c) = o01;
        *(float2*)(ob + (size_t)r1 * D_ + c) = o23;
    }
}

// ---------------------------------------------------------------------------
extern "C" void kernel_launch(void* const* d_in, const int* in_sizes, int n_in,
                              void* d_out, int out_size)
{
    const float* q = (const float*)d_in[0];
    const float* k = (const float*)d_in[1];
    const float* v = (const float*)d_in[2];
    int base = (in_sizes[3] == 36) ? 3 : 6;
    const float* pw  = (const float*)d_in[base + 0];
    const float* pb  = (const float*)d_in[base + 1];
    const float* g1  = (const float*)d_in[base + 2];
    const float* b1  = (const float*)d_in[base + 3];
    const float* w1  = (const float*)d_in[base + 4];
    const float* bb1 = (const float*)d_in[base + 5];
    const float* g2  = (const float*)d_in[base + 6];
    const float* b2  = (const float*)d_in[base + 7];
    const float* w2  = (const float*)d_in[base + 8];
    const float* bb2 = (const float*)d_in[base + 9];
    const float* g3  = (const float*)d_in[base + 10];
    const float* b3  = (const float*)d_in[base + 11];
    const float* w3  = (const float*)d_in[base + 12];
    const float* bb3 = (const float*)d_in[base + 13];
    float* out = (float*)d_out;

    cudaFuncSetAttribute(attn_kernel, cudaFuncAttributeMaxDynamicSharedMemorySize, SMEM_SZ);

    prep_kernel<<<BH_ + 1, 256>>>(k, v, pw, pb, g1, b1, w1, bb1,
                                  g2, b2, w2, bb2, g3, b3, w3, bb3);

    dim3 grid(N_ / 128, H_, B_);
    attn_kernel<<<grid, 256, SMEM_SZ>>>(q, out);
}

// round 7
// speedup vs baseline: 1.7282x; 1.1273x over previous
#include <cuda_runtime.h>
#include <cuda_fp16.h>
#include <stdint.h>

#define B_    64
#define H_    6
#define N_    512
#define D_    32
#define NIDX  43
#define BH_   384
#define LOG2E 1.4426950408889634f

// attn smem: K image 32KB | V image 32 rows x 2112B | bias
#define SK_OFF   0
#define SV_OFF   32768
#define VROW_U   132                    // uint4 per V^T d-row (128 used + 4 pad)
#define SB_OFF   (SV_OFF + D_*VROW_U*16)   // 100352
#define SMEM_SZ  (SB_OFF + 192)            // 100544 -> 2 CTAs/SM

#define PREP_SMEM (512*33*4)            // 67584

// gmem images:
// K: [bh][n(512)][le(4)] u4 = f16x2{c0,c0+1},{c0+8,c0+9},{16+c0,..},{16+c0+8,..}, c0=le*2
// V: [bh][d(32)][w(128)] u4 = {hi(v0,v1), hi(v8,v9), lo(v0,v1), lo(v8,v9)}, kv0=(w>>2)*16+(w&3)*2
__device__ uint4 g_K[BH_ * N_ * 4];
__device__ uint4 g_V[BH_ * D_ * 128];
__device__ float g_pos[H_ * NIDX];

// ---------------- helpers ----------------
__device__ __forceinline__ uint32_t pkf16(float x0, float x1) {
    uint32_t r; asm("cvt.rn.f16x2.f32 %0, %1, %2;" : "=r"(r) : "f"(x1), "f"(x0)); return r;
}
__device__ __forceinline__ void splitf16(float x0, float x1, uint32_t& hi, uint32_t& lo) {
    hi = pkf16(x0, x1);
    __half2 h = *reinterpret_cast<__half2*>(&hi);
    lo = pkf16(x0 - __half2float(h.x), x1 - __half2float(h.y));
}
__device__ __forceinline__ float ex2f(float x) {
    float y; asm("ex2.approx.f32 %0, %1;" : "=f"(y) : "f"(x)); return y;
}
__device__ __forceinline__ void mma_f16(float c[4], const uint32_t a[4], uint32_t b0, uint32_t b1) {
    asm volatile(
        "mma.sync.aligned.m16n8k16.row.col.f32.f16.f16.f32 "
        "{%0,%1,%2,%3}, {%4,%5,%6,%7}, {%8,%9}, {%0,%1,%2,%3};\n"
        : "+f"(c[0]), "+f"(c[1]), "+f"(c[2]), "+f"(c[3])
        : "r"(a[0]), "r"(a[1]), "r"(a[2]), "r"(a[3]), "r"(b0), "r"(b1));
}
__device__ __forceinline__ void cp16(uint32_t dst, const void* src) {
    asm volatile("cp.async.cg.shared.global [%0], [%1], 16;" :: "r"(dst), "l"(src));
}
#define CP_COMMIT() asm volatile("cp.async.commit_group;" ::: "memory")
#define CP_WAIT0()  asm volatile("cp.async.wait_group 0;" ::: "memory")

// ---------------------------------------------------------------------------
// Kernel 0: prep — block 0: bias MLP; blocks 1..384: K/V fp16 images
// ---------------------------------------------------------------------------
__device__ __forceinline__ void ln_relu12(const float* x, const float* g, const float* b, float* y) {
    float mu = 0.f;
    #pragma unroll
    for (int j = 0; j < 12; j++) mu += x[j];
    mu *= (1.f / 12.f);
    float var = 0.f;
    #pragma unroll
    for (int j = 0; j < 12; j++) { float d = x[j] - mu; var += d * d; }
    var *= (1.f / 12.f);
    float inv = rsqrtf(var + 1e-5f);
    #pragma unroll
    for (int j = 0; j < 12; j++) {
        float t = (x[j] - mu) * inv * g[j] + b[j];
        y[j] = t > 0.f ? t : 0.f;
    }
}

__global__ __launch_bounds__(256) void prep_kernel(
    const float* __restrict__ k, const float* __restrict__ v,
    const float* __restrict__ pw,  const float* __restrict__ pb,
    const float* __restrict__ g1,  const float* __restrict__ b1,
    const float* __restrict__ w1,  const float* __restrict__ bb1,
    const float* __restrict__ g2,  const float* __restrict__ b2,
    const float* __restrict__ w2,  const float* __restrict__ bb2,
    const float* __restrict__ g3,  const float* __restrict__ b3,
    const float* __restrict__ w3,  const float* __restrict__ bb3)
{
    extern __shared__ float sh[];
    const int t = threadIdx.x;

    if (blockIdx.x == 0) {
        if (t < 36)  sh[t] = pw[t];
        if (t < 12) {
            sh[36+t]=pb[t];  sh[48+t]=g1[t]; sh[60+t]=b1[t]; sh[216+t]=bb1[t];
            sh[228+t]=g2[t]; sh[240+t]=b2[t]; sh[396+t]=bb2[t];
            sh[408+t]=g3[t]; sh[420+t]=b3[t];
        }
        if (t < 144) { sh[72+t]=w1[t]; sh[252+t]=w2[t]; }
        if (t < 72)  sh[432+t] = w3[t];
        if (t < 6)   sh[504+t] = bb3[t];
        __syncthreads();
        if (t < NIDX) {
            float c0 = -7.0f, c1 = (float)(t / 15) - 7.0f, c2 = (float)(t % 15) - 7.0f;
            float x[12], y[12];
            #pragma unroll
            for (int j = 0; j < 12; j++)
                x[j] = c0 * sh[j] + c1 * sh[12 + j] + c2 * sh[24 + j] + sh[36 + j];
            ln_relu12(x, sh+48, sh+60, y);
            #pragma unroll
            for (int j = 0; j < 12; j++) {
                float s = sh[216 + j];
                #pragma unroll
                for (int i = 0; i < 12; i++) s += y[i] * sh[72 + i * 12 + j];
                x[j] = s;
            }
            ln_relu12(x, sh+228, sh+240, y);
            #pragma unroll
            for (int j = 0; j < 12; j++) {
                float s = sh[396 + j];
                #pragma unroll
                for (int i = 0; i < 12; i++) s += y[i] * sh[252 + i * 12 + j];
                x[j] = s;
            }
            ln_relu12(x, sh+408, sh+420, y);
            #pragma unroll
            for (int h = 0; h < H_; h++) {
                float s = sh[504 + h];
                #pragma unroll
                for (int i = 0; i < 12; i++) s += y[i] * sh[432 + i * H_ + h];
                g_pos[h * NIDX + t] = s;
            }
        }
        return;
    }

    const int bh = blockIdx.x - 1;
    const float* kb = k + (size_t)bh * N_ * D_;
    const float* vb = v + (size_t)bh * N_ * D_;

    // K image
    for (int i = t; i < N_ * 4; i += 256) {
        int n = i >> 2, le = i & 3, c0 = le * 2;
        const float* row = kb + (size_t)n * D_;
        float2 f0 = *(const float2*)(row + c0);
        float2 f1 = *(const float2*)(row + c0 + 8);
        float2 f2 = *(const float2*)(row + c0 + 16);
        float2 f3 = *(const float2*)(row + c0 + 24);
        uint4 w;
        w.x = pkf16(f0.x, f0.y); w.y = pkf16(f1.x, f1.y);
        w.z = pkf16(f2.x, f2.y); w.w = pkf16(f3.x, f3.y);
        g_K[(size_t)bh * (N_ * 4) + i] = w;
    }

    // V image: stage all 512x32 in smem, one sync, transpose-split out
    for (int i = t; i < N_ * D_; i += 256) {
        int kv = i >> 5, d = i & 31;
        sh[kv * 33 + d] = vb[i];
    }
    __syncthreads();
    for (int i = t; i < D_ * 128; i += 256) {
        int d = i >> 7, w_ = i & 127, kk = w_ >> 2, le = w_ & 3;
        int k0 = kk * 16 + le * 2;
        float v0 = sh[k0 * 33 + d],       v1 = sh[(k0 + 1) * 33 + d];
        float v8 = sh[(k0 + 8) * 33 + d], v9 = sh[(k0 + 9) * 33 + d];
        uint4 w;
        splitf16(v0, v1, w.x, w.z);
        splitf16(v8, v9, w.y, w.w);
        g_V[(size_t)bh * (D_ * 128) + i] = w;
    }
}

// ---------------------------------------------------------------------------
// Kernel 1: flash attention — fully resident KV, zero in-loop syncs
//   QK 1-pass fp16, PV 2-pass (V split), no-max exp2 softmax, bias in regs
// ---------------------------------------------------------------------------
__global__ __launch_bounds__(256, 2) void attn_kernel(
    const float* __restrict__ q, float* __restrict__ out)
{
    extern __shared__ unsigned char smem[];
    uint32_t sb;
    asm("{ .reg .u64 t; cvta.to.shared.u64 t, %1; cvt.u32.u64 %0, t; }" : "=r"(sb) : "l"(smem));
    float* biasSm = (float*)(smem + SB_OFF);

    const int qt = blockIdx.x, head = blockIdx.y, batch = blockIdx.z;
    const int bh = batch * H_ + head;
    const size_t bhOff = (size_t)bh * N_ * D_;
    const float* qb = q + bhOff;
    const int tid = threadIdx.x;

    if (tid < NIDX) biasSm[tid] = g_pos[head * NIDX + tid] * LOG2E;

    // one-shot KV fill
    {
        const uint4* gk = g_K + (size_t)bh * (N_ * 4);
        const uint4* gv = g_V + (size_t)bh * (D_ * 128);
        for (int i = tid; i < N_ * 4; i += 256)
            cp16(sb + SK_OFF + i * 16, gk + i);
        for (int i = tid; i < D_ * 128; i += 256) {
            int d = i >> 7, w_ = i & 127;
            cp16(sb + SV_OFF + (d * VROW_U + w_) * 16, gv + i);
        }
        CP_COMMIT();
    }

    const int warp = tid >> 5, lane = tid & 31;
    const int lq = lane >> 2, le = lane & 3, e0 = le * 2;
    const int r0 = qt * 128 + warp * 16 + lq;
    const int r1 = r0 + 8;
    const int sq0 = (r0 >> 6) + ((r0 >> 3) & 7) + (r0 & 7);

    // Q fragments (single fp16, scale folded into log2 domain)
    const float scale = 0.17677669529663687f * LOG2E;
    uint32_t aq[2][4];
    #pragma unroll
    for (int ks = 0; ks < 2; ks++) {
        int cb = ks * 16 + e0;
        aq[ks][0] = pkf16(qb[(size_t)r0 * D_ + cb] * scale,     qb[(size_t)r0 * D_ + cb + 1] * scale);
        aq[ks][1] = pkf16(qb[(size_t)r1 * D_ + cb] * scale,     qb[(size_t)r1 * D_ + cb + 1] * scale);
        aq[ks][2] = pkf16(qb[(size_t)r0 * D_ + cb + 8] * scale, qb[(size_t)r0 * D_ + cb + 9] * scale);
        aq[ks][3] = pkf16(qb[(size_t)r1 * D_ + cb + 8] * scale, qb[(size_t)r1 * D_ + cb + 9] * scale);
    }

    CP_WAIT0();
    __syncthreads();

    // bias window into registers: idx(row,u') = A1 - u'
    const int A1 = sq0 + 22 - e0;          // in [16,42]
    float br[17];
    #pragma unroll
    for (int u = 0; u < 17; u++) br[u] = biasSm[A1 - u];

    const uint4* Ks = (const uint4*)(smem + SK_OFF);
    const uint4* Vs = (const uint4*)(smem + SV_OFF);

    float O[4][4];
    #pragma unroll
    for (int d = 0; d < 4; d++)
        #pragma unroll
        for (int j = 0; j < 4; j++) O[d][j] = 0.f;
    float l0 = 0.f, l1 = 0.f;

    #pragma unroll
    for (int ch64 = 0; ch64 < 8; ch64++) {
        float S[8][4];
        #pragma unroll
        for (int nt = 0; nt < 8; nt++) {
            S[nt][0] = br[ch64 + nt + 1];   // r0, col e0
            S[nt][1] = br[ch64 + nt + 2];   // r0, col e0+1
            S[nt][2] = br[ch64 + nt];       // r1, col e0
            S[nt][3] = br[ch64 + nt + 1];   // r1, col e0+1
        }
        // S += Q K^T (1-pass fp16)
        #pragma unroll
        for (int nt = 0; nt < 8; nt++) {
            uint4 w = Ks[(ch64 * 64 + nt * 8 + lq) * 4 + le];
            mma_f16(S[nt], aq[0], w.x, w.y);
            mma_f16(S[nt], aq[1], w.z, w.w);
        }
        // exp2 (no max) + row sums
        float ps0 = 0.f, ps1 = 0.f;
        #pragma unroll
        for (int nt = 0; nt < 8; nt++) {
            S[nt][0] = ex2f(S[nt][0]); S[nt][1] = ex2f(S[nt][1]);
            S[nt][2] = ex2f(S[nt][2]); S[nt][3] = ex2f(S[nt][3]);
            ps0 += S[nt][0] + S[nt][1];
            ps1 += S[nt][2] + S[nt][3];
        }
        l0 += ps0; l1 += ps1;
        // O += P V (P single fp16, V hi/lo)
        #pragma unroll
        for (int kk = 0; kk < 4; kk++) {
            uint32_t ap[4];
            ap[0] = pkf16(S[2 * kk][0],     S[2 * kk][1]);
            ap[1] = pkf16(S[2 * kk][2],     S[2 * kk][3]);
            ap[2] = pkf16(S[2 * kk + 1][0], S[2 * kk + 1][1]);
            ap[3] = pkf16(S[2 * kk + 1][2], S[2 * kk + 1][3]);
            const int wbase = (ch64 * 4 + kk) * 4 + le;
            #pragma unroll
            for (int dt = 0; dt < 4; dt++) {
                uint4 w = Vs[(dt * 8 + lq) * VROW_U + wbase];
                mma_f16(O[dt], ap, w.x, w.y);   // V hi
                mma_f16(O[dt], ap, w.z, w.w);   // V lo
            }
        }
    }

    // finalize
    l0 += __shfl_xor_sync(0xffffffffu, l0, 1);
    l0 += __shfl_xor_sync(0xffffffffu, l0, 2);
    l1 += __shfl_xor_sync(0xffffffffu, l1, 1);
    l1 += __shfl_xor_sync(0xffffffffu, l1, 2);
    float i0 = 1.f / l0, i1 = 1.f / l1;
    float* ob = out + bhOff;
    #pragma unroll
    for (int dt = 0; dt < 4; dt++) {
        int c = dt * 8 + e0;
        float2 o01; o01.x = O[dt][0] * i0; o01.y = O[dt][1] * i0;
        float2 o23; o23.x = O[dt][2] * i1; o23.y = O[dt][3] * i1;
        *(float2*)(ob + (size_t)r0 * D_ + c) = o01;
        *(float2*)(ob + (size_t)r1 * D_ + c) = o23;
    }
}

// ---------------------------------------------------------------------------
extern "C" void kernel_launch(void* const* d_in, const int* in_sizes, int n_in,
                              void* d_out, int out_size)
{
    const float* q = (const float*)d_in[0];
    const float* k = (const float*)d_in[1];
    const float* v = (const float*)d_in[2];
    int base = (in_sizes[3] == 36) ? 3 : 6;
    const float* pw  = (const float*)d_in[base + 0];
    const float* pb  = (const float*)d_in[base + 1];
    const float* g1  = (const float*)d_in[base + 2];
    const float* b1  = (const float*)d_in[base + 3];
    const float* w1  = (const float*)d_in[base + 4];
    const float* bb1 = (const float*)d_in[base + 5];
    const float* g2  = (const float*)d_in[base + 6];
    const float* b2  = (const float*)d_in[base + 7];
    const float* w2  = (const float*)d_in[base + 8];
    const float* bb2 = (const float*)d_in[base + 9];
    const float* g3  = (const float*)d_in[base + 10];
    const float* b3  = (const float*)d_in[base + 11];
    const float* w3  = (const float*)d_in[base + 12];
    const float* bb3 = (const float*)d_in[base + 13];
    float* out = (float*)d_out;

    cudaFuncSetAttribute(prep_kernel, cudaFuncAttributeMaxDynamicSharedMemorySize, PREP_SMEM);
    cudaFuncSetAttribute(attn_kernel, cudaFuncAttributeMaxDynamicSharedMemorySize, SMEM_SZ);

    prep_kernel<<<BH_ + 1, 256, PREP_SMEM>>>(k, v, pw, pb, g1, b1, w1, bb1,
                                             g2, b2, w2, bb2, g3, b3, w3, bb3);

    dim3 grid(N_ / 128, H_, B_);
    attn_kernel<<<grid, 256, SMEM_SZ>>>(q, out);
}

// round 9
// speedup vs baseline: 1.8227x; 1.0547x over previous
#include <cuda_runtime.h>
#include <cuda_fp16.h>
#include <stdint.h>

#define B_    64
#define H_    6
#define N_    512
#define D_    32
#define NIDX  43
#define BH_   384
#define LOG2E 1.4426950408889634f

// attn smem: K image 32KB | V image 32 rows x 68 u4 (64 used + 4 pad) | bias
#define SK_OFF   0
#define SV_OFF   32768
#define VROW_U   68
#define SB_OFF   (SV_OFF + D_*VROW_U*16)   // 32768 + 34816 = 67584
#define SMEM_SZ  (SB_OFF + 192)            // 67776 -> 2 CTAs/SM
#define PREP_SMEM (128*33*4)               // 16896

// gmem images:
// K: [bh][n(512)][le(4)] u4 = f16x2{c0,c0+1},{c0+8,c0+9},{16+c0,16+c0+1},{16+c0+8,16+c0+9}, c0=le*2
// V: [bh][d(32)][w(64)] u4; w = kp*4+le, kp in [0,16), k0 = 32*kp+2*le:
//    {v(k0),v(k0+1)},{v(k0+8),v(k0+9)},{v(k0+16),v(k0+17)},{v(k0+24),v(k0+25)}
__device__ uint4 g_K[BH_ * N_ * 4];
__device__ uint4 g_V[BH_ * D_ * 64];
__device__ float g_pos[H_ * NIDX];

// ---------------- helpers ----------------
__device__ __forceinline__ uint32_t pkf16(float x0, float x1) {
    uint32_t r; asm("cvt.rn.f16x2.f32 %0, %1, %2;" : "=r"(r) : "f"(x1), "f"(x0)); return r;
}
__device__ __forceinline__ float ex2f(float x) {
    float y; asm("ex2.approx.f32 %0, %1;" : "=f"(y) : "f"(x)); return y;
}
__device__ __forceinline__ void mma_f16(float c[4], const uint32_t a[4], uint32_t b0, uint32_t b1) {
    asm volatile(
        "mma.sync.aligned.m16n8k16.row.col.f32.f16.f16.f32 "
        "{%0,%1,%2,%3}, {%4,%5,%6,%7}, {%8,%9}, {%0,%1,%2,%3};\n"
        : "+f"(c[0]), "+f"(c[1]), "+f"(c[2]), "+f"(c[3])
        : "r"(a[0]), "r"(a[1]), "r"(a[2]), "r"(a[3]), "r"(b0), "r"(b1));
}
__device__ __forceinline__ void cp16(uint32_t dst, const void* src) {
    asm volatile("cp.async.cg.shared.global [%0], [%1], 16;" :: "r"(dst), "l"(src));
}
#define CP_COMMIT() asm volatile("cp.async.commit_group;" ::: "memory")
#define CP_WAIT0()  asm volatile("cp.async.wait_group 0;" ::: "memory")

__device__ __forceinline__ void ln_relu12(const float* x, const float* g, const float* b, float* y) {
    float mu = 0.f;
    #pragma unroll
    for (int j = 0; j < 12; j++) mu += x[j];
    mu *= (1.f / 12.f);
    float var = 0.f;
    #pragma unroll
    for (int j = 0; j < 12; j++) { float d = x[j] - mu; var += d * d; }
    var *= (1.f / 12.f);
    float inv = rsqrtf(var + 1e-5f);
    #pragma unroll
    for (int j = 0; j < 12; j++) {
        float t = (x[j] - mu) * inv * g[j] + b[j];
        y[j] = t > 0.f ? t : 0.f;
    }
}

// ---------------------------------------------------------------------------
// Kernel 0: prep — block 0: bias MLP; blocks 1..1536: one (bh, 128-kv chunk)
// ---------------------------------------------------------------------------
__global__ __launch_bounds__(256) void prep_kernel(
    const float* __restrict__ k, const float* __restrict__ v,
    const float* __restrict__ pw,  const float* __restrict__ pb,
    const float* __restrict__ g1,  const float* __restrict__ b1,
    const float* __restrict__ w1,  const float* __restrict__ bb1,
    const float* __restrict__ g2,  const float* __restrict__ b2,
    const float* __restrict__ w2,  const float* __restrict__ bb2,
    const float* __restrict__ g3,  const float* __restrict__ b3,
    const float* __restrict__ w3,  const float* __restrict__ bb3)
{
    extern __shared__ float sh[];
    const int t = threadIdx.x;

    if (blockIdx.x == 0) {
        if (t < 36)  sh[t] = pw[t];
        if (t < 12) {
            sh[36+t]=pb[t];  sh[48+t]=g1[t]; sh[60+t]=b1[t]; sh[216+t]=bb1[t];
            sh[228+t]=g2[t]; sh[240+t]=b2[t]; sh[396+t]=bb2[t];
            sh[408+t]=g3[t]; sh[420+t]=b3[t];
        }
        if (t < 144) { sh[72+t]=w1[t]; sh[252+t]=w2[t]; }
        if (t < 72)  sh[432+t] = w3[t];
        if (t < 6)   sh[504+t] = bb3[t];
        __syncthreads();
        if (t < NIDX) {
            float c0 = -7.0f, c1 = (float)(t / 15) - 7.0f, c2 = (float)(t % 15) - 7.0f;
            float x[12], y[12];
            #pragma unroll
            for (int j = 0; j < 12; j++)
                x[j] = c0 * sh[j] + c1 * sh[12 + j] + c2 * sh[24 + j] + sh[36 + j];
            ln_relu12(x, sh+48, sh+60, y);
            #pragma unroll
            for (int j = 0; j < 12; j++) {
                float s = sh[216 + j];
                #pragma unroll
                for (int i = 0; i < 12; i++) s += y[i] * sh[72 + i * 12 + j];
                x[j] = s;
            }
            ln_relu12(x, sh+228, sh+240, y);
            #pragma unroll
            for (int j = 0; j < 12; j++) {
                float s = sh[396 + j];
                #pragma unroll
                for (int i = 0; i < 12; i++) s += y[i] * sh[252 + i * 12 + j];
                x[j] = s;
            }
            ln_relu12(x, sh+408, sh+420, y);
            #pragma unroll
            for (int h = 0; h < H_; h++) {
                float s = sh[504 + h];
                #pragma unroll
                for (int i = 0; i < 12; i++) s += y[i] * sh[432 + i * H_ + h];
                g_pos[h * NIDX + t] = s;
            }
        }
        return;
    }

    const int bi = blockIdx.x - 1;
    const int bh = bi >> 2, c = bi & 3;      // kv rows 128c..128c+127 of this bh
    const float* kb = k + (size_t)bh * N_ * D_ + (size_t)(128 * c) * D_;
    const float* vb = v + (size_t)bh * N_ * D_ + (size_t)(128 * c) * D_;

    // K image (128 rows of this chunk)
    for (int i = t; i < 128 * 4; i += 256) {
        int n = i >> 2, le = i & 3, c0 = le * 2;
        const float* row = kb + (size_t)n * D_;
        float2 f0 = *(const float2*)(row + c0);
        float2 f1 = *(const float2*)(row + c0 + 8);
        float2 f2 = *(const float2*)(row + c0 + 16);
        float2 f3 = *(const float2*)(row + c0 + 24);
        uint4 w;
        w.x = pkf16(f0.x, f0.y); w.y = pkf16(f1.x, f1.y);
        w.z = pkf16(f2.x, f2.y); w.w = pkf16(f3.x, f3.y);
        g_K[(size_t)bh * (N_ * 4) + (size_t)(128 * c) * 4 + i] = w;
    }

    // V: stage this chunk's 128x32 fp32 in smem, transpose-pack 16 u4 per d-row
    for (int i = t; i < 128 * D_; i += 256) {
        int kv = i >> 5, d = i & 31;
        sh[kv * 33 + d] = vb[i];
    }
    __syncthreads();
    for (int i = t; i < D_ * 16; i += 256) {       // 512 u4 per chunk
        int d = i >> 4, wl = i & 15;               // wl = kpl*4 + le, kpl in [0,4)
        int kpl = wl >> 2, le = wl & 3;
        int k0 = 32 * kpl + 2 * le;                // local kv base
        uint4 w;
        w.x = pkf16(sh[(k0 +  0) * 33 + d], sh[(k0 +  1) * 33 + d]);
        w.y = pkf16(sh[(k0 +  8) * 33 + d], sh[(k0 +  9) * 33 + d]);
        w.z = pkf16(sh[(k0 + 16) * 33 + d], sh[(k0 + 17) * 33 + d]);
        w.w = pkf16(sh[(k0 + 24) * 33 + d], sh[(k0 + 25) * 33 + d]);
        // global w = (4c + kpl)*4 + le = 16c + wl
        g_V[(size_t)bh * (D_ * 64) + d * 64 + 16 * c + wl] = w;
    }
}

// ---------------------------------------------------------------------------
// Kernel 1: flash attention — resident KV, QK 1-pass, PV 1-pass, exp2 softmax
// ---------------------------------------------------------------------------
__global__ __launch_bounds__(256, 2) void attn_kernel(
    const float* __restrict__ q, float* __restrict__ out)
{
    extern __shared__ unsigned char smem[];
    uint32_t sb;
    asm("{ .reg .u64 t; cvta.to.shared.u64 t, %1; cvt.u32.u64 %0, t; }" : "=r"(sb) : "l"(smem));
    float* biasSm = (float*)(smem + SB_OFF);

    const int qt = blockIdx.x, head = blockIdx.y, batch = blockIdx.z;
    const int bh = batch * H_ + head;
    const size_t bhOff = (size_t)bh * N_ * D_;
    const float* qb = q + bhOff;
    const int tid = threadIdx.x;

    if (tid < NIDX) biasSm[tid] = g_pos[head * NIDX + tid] * LOG2E;

    // one-shot KV fill
    {
        const uint4* gk = g_K + (size_t)bh * (N_ * 4);
        const uint4* gv = g_V + (size_t)bh * (D_ * 64);
        for (int i = tid; i < N_ * 4; i += 256)
            cp16(sb + SK_OFF + i * 16, gk + i);
        for (int i = tid; i < D_ * 64; i += 256) {
            int d = i >> 6, w_ = i & 63;
            cp16(sb + SV_OFF + (d * VROW_U + w_) * 16, gv + i);
        }
        CP_COMMIT();
    }

    const int warp = tid >> 5, lane = tid & 31;
    const int lq = lane >> 2, le = lane & 3, e0 = le * 2;
    const int r0 = qt * 128 + warp * 16 + lq;
    const int r1 = r0 + 8;
    const int sq0 = (r0 >> 6) + ((r0 >> 3) & 7) + (r0 & 7);

    // Q fragments (single fp16, scale folded into log2 domain)
    const float scale = 0.17677669529663687f * LOG2E;
    uint32_t aq[2][4];
    #pragma unroll
    for (int ks = 0; ks < 2; ks++) {
        int cb = ks * 16 + e0;
        aq[ks][0] = pkf16(qb[(size_t)r0 * D_ + cb] * scale,     qb[(size_t)r0 * D_ + cb + 1] * scale);
        aq[ks][1] = pkf16(qb[(size_t)r1 * D_ + cb] * scale,     qb[(size_t)r1 * D_ + cb + 1] * scale);
        aq[ks][2] = pkf16(qb[(size_t)r0 * D_ + cb + 8] * scale, qb[(size_t)r0 * D_ + cb + 9] * scale);
        aq[ks][3] = pkf16(qb[(size_t)r1 * D_ + cb + 8] * scale, qb[(size_t)r1 * D_ + cb + 9] * scale);
    }

    CP_WAIT0();
    __syncthreads();

    // bias window in registers: S-init index = A1 - (ch64 + nt + {0,1,2}) style
    const int A1 = sq0 + 22 - e0;          // in [16,42]
    float br[17];
    #pragma unroll
    for (int u = 0; u < 17; u++) br[u] = biasSm[A1 - u];

    const uint4* Ks = (const uint4*)(smem + SK_OFF);
    const uint4* Vs = (const uint4*)(smem + SV_OFF);

    float O[4][4];
    #pragma unroll
    for (int d = 0; d < 4; d++)
        #pragma unroll
        for (int j = 0; j < 4; j++) O[d][j] = 0.f;
    float l0 = 0.f, l1 = 0.f;

    #pragma unroll
    for (int ch64 = 0; ch64 < 8; ch64++) {
        float S[8][4];
        #pragma unroll
        for (int nt = 0; nt < 8; nt++) {
            S[nt][0] = br[ch64 + nt + 1];   // r0, col e0
            S[nt][1] = br[ch64 + nt + 2];   // r0, col e0+1
            S[nt][2] = br[ch64 + nt];       // r1, col e0
            S[nt][3] = br[ch64 + nt + 1];   // r1, col e0+1
        }
        // S += Q K^T (1-pass fp16)
        #pragma unroll
        for (int nt = 0; nt < 8; nt++) {
            uint4 w = Ks[(ch64 * 64 + nt * 8 + lq) * 4 + le];
            mma_f16(S[nt], aq[0], w.x, w.y);
            mma_f16(S[nt], aq[1], w.z, w.w);
        }
        // exp2 (no max; logits bounded) + row sums
        float ps0 = 0.f, ps1 = 0.f;
        #pragma unroll
        for (int nt = 0; nt < 8; nt++) {
            S[nt][0] = ex2f(S[nt][0]); S[nt][1] = ex2f(S[nt][1]);
            S[nt][2] = ex2f(S[nt][2]); S[nt][3] = ex2f(S[nt][3]);
            ps0 += S[nt][0] + S[nt][1];
            ps1 += S[nt][2] + S[nt][3];
        }
        l0 += ps0; l1 += ps1;
        // O += P V (1-pass; each u4 feeds two 16-kv k-blocks)
        #pragma unroll
        for (int kp2 = 0; kp2 < 2; kp2++) {
            const int j0 = kp2 * 2, j1 = j0 + 1;   // k-blocks (16 kv each)
            uint32_t ap0[4], ap1[4];
            ap0[0] = pkf16(S[2*j0][0],   S[2*j0][1]);
            ap0[1] = pkf16(S[2*j0][2],   S[2*j0][3]);
            ap0[2] = pkf16(S[2*j0+1][0], S[2*j0+1][1]);
            ap0[3] = pkf16(S[2*j0+1][2], S[2*j0+1][3]);
            ap1[0] = pkf16(S[2*j1][0],   S[2*j1][1]);
            ap1[1] = pkf16(S[2*j1][2],   S[2*j1][3]);
            ap1[2] = pkf16(S[2*j1+1][0], S[2*j1+1][1]);
            ap1[3] = pkf16(S[2*j1+1][2], S[2*j1+1][3]);
            const int wb = (ch64 * 2 + kp2) * 4 + le;   // kp = ch64*2+kp2
            #pragma unroll
            for (int dt = 0; dt < 4; dt++) {
                uint4 w = Vs[(dt * 8 + lq) * VROW_U + wb];
                mma_f16(O[dt], ap0, w.x, w.y);
                mma_f16(O[dt], ap1, w.z, w.w);
            }
        }
    }

    // finalize
    l0 += __shfl_xor_sync(0xffffffffu, l0, 1);
    l0 += __shfl_xor_sync(0xffffffffu, l0, 2);
    l1 += __shfl_xor_sync(0xffffffffu, l1, 1);
    l1 += __shfl_xor_sync(0xffffffffu, l1, 2);
    float i0 = 1.f / l0, i1 = 1.f / l1;
    float* ob = out + bhOff;
    #pragma unroll
    for (int dt = 0; dt < 4; dt++) {
        int c = dt * 8 + e0;
        float2 o01; o01.x = O[dt][0] * i0; o01.y = O[dt][1] * i0;
        float2 o23; o23.x = O[dt][2] * i1; o23.y = O[dt][3] * i1;
        *(float2*)(ob + (size_t)r0 * D_ + c) = o01;
        *(float2*)(ob + (size_t)r1 * D_ + c) = o23;
    }
}

// ---------------------------------------------------------------------------
extern "C" void kernel_launch(void* const* d_in, const int* in_sizes, int n_in,
                              void* d_out, int out_size)
{
    const float* q = (const float*)d_in[0];
    const float* k = (const float*)d_in[1];
    const float* v = (const float*)d_in[2];
    int base = (in_sizes[3] == 36) ? 3 : 6;
    const float* pw  = (const float*)d_in[base + 0];
    const float* pb  = (const float*)d_in[base + 1];
    const float* g1  = (const float*)d_in[base + 2];
    const float* b1  = (const float*)d_in[base + 3];
    const float* w1  = (const float*)d_in[base + 4];
    const float* bb1 = (const float*)d_in[base + 5];
    const float* g2  = (const float*)d_in[base + 6];
    const float* b2  = (const float*)d_in[base + 7];
    const float* w2  = (const float*)d_in[base + 8];
    const float* bb2 = (const float*)d_in[base + 9];
    const float* g3  = (const float*)d_in[base + 10];
    const float* b3  = (const float*)d_in[base + 11];
    const float* w3  = (const float*)d_in[base + 12];
    const float* bb3 = (const float*)d_in[base + 13];
    float* out = (float*)d_out;

    cudaFuncSetAttribute(prep_kernel, cudaFuncAttributeMaxDynamicSharedMemorySize, PREP_SMEM);
    cudaFuncSetAttribute(attn_kernel, cudaFuncAttributeMaxDynamicSharedMemorySize, SMEM_SZ);

    prep_kernel<<<BH_ * 4 + 1, 256, PREP_SMEM>>>(k, v, pw, pb, g1, b1, w1, bb1,
                                                 g2, b2, w2, bb2, g3, b3, w3, bb3);

    dim3 grid(N_ / 128, H_, B_);
    attn_kernel<<<grid, 256, SMEM_SZ>>>(q, out);
}